// round 9
// baseline (speedup 1.0000x reference)
#include <cuda_runtime.h>
#include <cstdint>
#include <cstddef>

// ---------------- problem constants ----------------
#define BS    8
#define NFEAT 64
#define NND   2048
#define JDIM  3
#define CH    128                  // 2*NOUT
#define KDIM  6144                 // NND*JDIM
#define ZN    (BS*CH*NND)          // 2097152 zbn elements
#define CHUNK 32                   // fp32 of K per chunk (128 B per row)
#define NCH   (KDIM/CHUNK)         // 192
#define STAGES 5
#define LOOKAHEAD 4
#define MT    128                  // m-rows per CTA tile
#define WTILEB (MT*CHUNK*4)        // 16384 W tile bytes
#define PTILEB (128*CHUNK*4)       // 16384 P tile bytes
#define STAGEB (WTILEB+PTILEB)     // 32768
#define DYN2  (STAGES*STAGEB)      // 163840
#define THR2  256                  // 8 warps: 2x2 grid of 64x64 tiles, k-split pairs
#define EXST  68                   // padded row stride (floats) for pair exchange
#define DYN1  147456               // k1: As 32KB + Xs 16KB + stage 96KB

// ---------------- device scratch ----------------
__device__ float g_P[(size_t)BS*CH*KDIM];   // 25.2 MB
__device__ float g_z[(size_t)ZN];           // 8.4 MB
__device__ float g_pS1[256*CH];             // per (cta, wy) channel partials
__device__ float g_pS2[256*CH];
__device__ float g_misc[2];                 // total, M0
__device__ float g_scale[CH];
__device__ float g_shift[CH];

// ---------------- helpers ----------------
__device__ __forceinline__ uint32_t smem_u32(const void* p) {
    uint32_t a;
    asm("{ .reg .u64 t; cvta.to.shared.u64 t, %1; cvt.u32.u64 %0, t; }" : "=r"(a) : "l"(p));
    return a;
}
__device__ __forceinline__ void cp_async16(uint32_t dst, const void* src) {
    asm volatile("cp.async.cg.shared.global [%0], [%1], 16;" :: "r"(dst), "l"(src) : "memory");
}
#define CP_COMMIT() asm volatile("cp.async.commit_group;" ::: "memory")
#define CP_WAIT(n)  asm volatile("cp.async.wait_group %0;" :: "n"(n) : "memory")

__device__ __forceinline__ void mma_tf32(float* d, const uint32_t* a, const uint32_t* b) {
    asm volatile(
        "mma.sync.aligned.m16n8k8.row.col.f32.tf32.tf32.f32 "
        "{%0,%1,%2,%3}, {%4,%5,%6,%7}, {%8,%9}, {%0,%1,%2,%3};"
        : "+f"(d[0]), "+f"(d[1]), "+f"(d[2]), "+f"(d[3])
        : "r"(a[0]), "r"(a[1]), "r"(a[2]), "r"(a[3]), "r"(b[0]), "r"(b[1]));
}
__device__ __forceinline__ void ldmx4(uint32_t* r, uint32_t addr) {
    asm volatile(
        "ldmatrix.sync.aligned.m8n8.x4.shared.b16 {%0,%1,%2,%3}, [%4];"
        : "=r"(r[0]), "=r"(r[1]), "=r"(r[2]), "=r"(r[3]) : "r"(addr));
}
__device__ __forceinline__ int segoff(int row, int seg) {   // seg = 16B unit 0..7
    return row*128 + ((seg ^ (row & 7)) << 4);
}

// ---------------- K0: init reductions ----------------
__global__ void k0_init(const float* __restrict__ Nb, const float* __restrict__ mask) {
    int tid = threadIdx.x;
    float acc = 0.0f;
    for (int i = tid; i < BS*NND; i += 256) acc += mask[i];
    __shared__ float red[256];
    red[tid] = acc;
    __syncthreads();
    for (int s = 128; s > 0; s >>= 1) {
        if (tid < s) red[tid] += red[tid + s];
        __syncthreads();
    }
    if (tid == 0) {
        float tot = 0.0f;
        for (int i = 0; i < BS; i++) tot += Nb[i];
        g_misc[0] = tot;
        g_misc[1] = red[0];
    }
}

// ---------------- dummy kernel: keeps k2 in the ncu capture slot ----------------
__global__ void k_nop() {}

// ---------------- K1: P[b,o,n*3+j] = sum_f C[o, j*64+f] * X[b,f,n] ----------------
__global__ void __launch_bounds__(256, 1)
k1_gemm(const float* __restrict__ X, const float* __restrict__ cv1_w,
        const float* __restrict__ cv2_w) {
    extern __shared__ float sm1[];
    float* As    = sm1;            // [64 f][128 o]
    float* Xs    = sm1 + 8192;     // [64 f][64 n]
    float* stage = sm1 + 12288;    // [128 o][192 k']
    int tid = threadIdx.x;
    int nt = blockIdx.x, b = blockIdx.y;

    #pragma unroll
    for (int i = 0; i < 4; i++) {
        int q = i*256 + tid;
        int n4 = q & 15;
        int f  = q >> 4;
        float4 v = __ldg((const float4*)(X + ((size_t)(b*NFEAT + f))*NND + nt*64 + n4*4));
        *(float4*)(Xs + f*64 + n4*4) = v;
    }

    int tx = tid & 15, ty = tid >> 4;

    for (int j = 0; j < JDIM; j++) {
        __syncthreads();
        #pragma unroll
        for (int i = 0; i < 8; i++) {
            int q = i*256 + tid;
            int o  = q & 127;
            int f4 = q >> 7;
            const float* src = ((o < 64) ? (cv2_w + o*192) : (cv1_w + (o-64)*192)) + j*64 + f4*4;
            float4 v = __ldg((const float4*)src);
            As[(f4*4+0)*128 + o] = v.x;
            As[(f4*4+1)*128 + o] = v.y;
            As[(f4*4+2)*128 + o] = v.z;
            As[(f4*4+3)*128 + o] = v.w;
        }
        __syncthreads();

        float acc[8][4];
        #pragma unroll
        for (int i = 0; i < 8; i++)
            #pragma unroll
            for (int u = 0; u < 4; u++) acc[i][u] = 0.0f;

        #pragma unroll 8
        for (int f = 0; f < 64; f++) {
            float a[8], bb[4];
            *(float4*)(a)   = *(const float4*)(As + f*128 + ty*8);
            *(float4*)(a+4) = *(const float4*)(As + f*128 + ty*8 + 4);
            *(float4*)(bb)  = *(const float4*)(Xs + f*64 + tx*4);
            #pragma unroll
            for (int i = 0; i < 8; i++)
                #pragma unroll
                for (int u = 0; u < 4; u++)
                    acc[i][u] = fmaf(a[i], bb[u], acc[i][u]);
        }
        #pragma unroll
        for (int i = 0; i < 8; i++) {
            int o = ty*8 + i;
            #pragma unroll
            for (int u = 0; u < 4; u++)
                stage[o*192 + (tx*4 + u)*3 + j] = acc[i][u];
        }
    }
    __syncthreads();

    #pragma unroll
    for (int i = 0; i < 24; i++) {
        int q = i*256 + tid;
        int row = q / 48, c4 = q % 48;
        float4 v = *(const float4*)(stage + row*192 + c4*4);
        *(float4*)(g_P + ((size_t)(b*CH + row))*KDIM + nt*192 + c4*4) = v;
    }
}

// ---------------- K2: D = W * P^T, k-split pairs, software-pipelined chunk ----------------
__device__ __forceinline__ void k2_load_stage(char* sm, const float* wsrc,
                                              const float* psrc, int c, int tid) {
    #pragma unroll
    for (int i = 0; i < 4; i++) {
        int q = i*THR2 + tid;
        int row = q >> 3, seg = q & 7;
        cp_async16(smem_u32(sm + segoff(row, seg)),
                   wsrc + (size_t)row*KDIM + c*CHUNK + seg*4);
    }
    #pragma unroll
    for (int i = 0; i < 4; i++) {
        int q = i*THR2 + tid;
        int row = q >> 3, seg = q & 7;
        cp_async16(smem_u32(sm + WTILEB + segoff(row, seg)),
                   psrc + (size_t)row*KDIM + c*CHUNK + seg*4);
    }
}

__global__ void __launch_bounds__(THR2, 1)
k2_gemm(const float* __restrict__ W, const float* __restrict__ cv1_b,
        const float* __restrict__ cv2_b, const float* __restrict__ mask,
        float* __restrict__ outW) {
    extern __shared__ char dyn2[];
    __shared__ float s_bias[CH];
    __shared__ float s_mask[MT];

    int tid = threadIdx.x;
    int wid = tid >> 5, lane = tid & 31;
    int p  = wid >> 1;                     // pair 0..3
    int h  = wid & 1;                      // k-half within pair
    int wy = p >> 1, wx = p & 1;           // 2x2 grid, 64x64 tiles
    int g = lane >> 2, tig = lane & 3;
    int mt = blockIdx.x, b = blockIdx.y;

    if (tid < CH) s_bias[tid] = (tid < 64) ? cv2_b[tid] : cv1_b[tid - 64];
    if (tid < MT) s_mask[tid] = mask[(size_t)b*NND + mt*MT + tid];

    const float* wsrc = W    + ((size_t)(b*NND + mt*MT))*KDIM;
    float*       wdst = outW + ((size_t)(b*NND + mt*MT))*KDIM;
    const float* psrc = g_P  + ((size_t)(b*CH))*KDIM;

    uint32_t dyn_u = smem_u32(dyn2);

    // ldmatrix offsets
    int mIdx = lane >> 3;
    uint32_t offA[4];
    #pragma unroll
    for (int mg = 0; mg < 4; mg++) {
        int rA = wy*64 + mg*16 + (mIdx & 1)*8 + (lane & 7);
        offA[mg] = (uint32_t)(rA*128 + ((((mIdx >> 1) ^ (rA & 7))) << 4));
    }
    uint32_t offB[4];
    #pragma unroll
    for (int hh = 0; hh < 4; hh++) {
        int ot = hh*2 + (mIdx >> 1);
        int rB = wx*64 + ot*8 + (lane & 7);
        offB[hh] = (uint32_t)(rB*128 + ((((mIdx & 1) ^ (rB & 7))) << 4));
    }

    float acc[4][8][4];
    #pragma unroll
    for (int t = 0; t < 4; t++)
        #pragma unroll
        for (int ot = 0; ot < 8; ot++)
            #pragma unroll
            for (int r = 0; r < 4; r++) acc[t][ot][r] = 0.0f;

    #pragma unroll
    for (int s = 0; s < LOOKAHEAD; s++) {
        k2_load_stage(dyn2 + s*STAGEB, wsrc, psrc, s, tid);
        CP_COMMIT();
    }

    uint32_t xo0 = (uint32_t)((h*2) << 5);
    uint32_t xo1 = (uint32_t)((h*2 + 1) << 5);

    for (int c = 0; c < NCH; c++) {
        CP_WAIT(LOOKAHEAD - 1);
        __syncthreads();

        uint32_t swu = dyn_u + (uint32_t)((c % STAGES)*STAGEB);
        uint32_t spu = swu + WTILEB;
        char*    sw  = dyn2 + (c % STAGES)*STAGEB;

        // --- fragments for k-step 0 ---
        uint32_t a0[4][4], b0[8][2];
        #pragma unroll
        for (int mg = 0; mg < 4; mg++)
            ldmx4(a0[mg], swu + (offA[mg] ^ xo0));
        #pragma unroll
        for (int hh = 0; hh < 4; hh++) {
            uint32_t r[4];
            ldmx4(r, spu + (offB[hh] ^ xo0));
            b0[hh*2][0] = r[0]; b0[hh*2][1] = r[1];
            b0[hh*2+1][0] = r[2]; b0[hh*2+1][1] = r[3];
        }

        // --- prefetch next chunk (into the buffer consumed at c-1) ---
        if (c + LOOKAHEAD < NCH)
            k2_load_stage(dyn2 + ((c + LOOKAHEAD) % STAGES)*STAGEB, wsrc, psrc,
                          c + LOOKAHEAD, tid);
        CP_COMMIT();

        // --- fused W copy-out ---
        #pragma unroll
        for (int i = 0; i < 4; i++) {
            int q = i*THR2 + tid;
            int row = q >> 3, seg = q & 7;
            float4 v = *(const float4*)(sw + segoff(row, seg));
            *(float4*)(wdst + (size_t)row*KDIM + c*CHUNK + seg*4) = v;
        }

        // --- fragments for k-step 1 ---
        uint32_t a1[4][4], b1[8][2];
        #pragma unroll
        for (int mg = 0; mg < 4; mg++)
            ldmx4(a1[mg], swu + (offA[mg] ^ xo1));
        #pragma unroll
        for (int hh = 0; hh < 4; hh++) {
            uint32_t r[4];
            ldmx4(r, spu + (offB[hh] ^ xo1));
            b1[hh*2][0] = r[0]; b1[hh*2][1] = r[1];
            b1[hh*2+1][0] = r[2]; b1[hh*2+1][1] = r[3];
        }

        // --- MMAs (long distance from their fragment loads) ---
        #pragma unroll
        for (int t = 0; t < 4; t++)
            #pragma unroll
            for (int ot = 0; ot < 8; ot++)
                mma_tf32(acc[t][ot], a0[t], b0[ot]);
        #pragma unroll
        for (int t = 0; t < 4; t++)
            #pragma unroll
            for (int ot = 0; ot < 8; ot++)
                mma_tf32(acc[t][ot], a1[t], b1[ot]);
    }

    // ---- pair merge: h=1 stores partial acc to padded smem, h=0 adds ----
    __syncthreads();   // all copy-out reads of stage buffers done
    float* ex = (float*)(dyn2) + p * (64*EXST);
    if (h == 1) {
        #pragma unroll
        for (int t = 0; t < 4; t++)
            #pragma unroll
            for (int ot = 0; ot < 8; ot++)
                #pragma unroll
                for (int r = 0; r < 4; r++) {
                    int row = t*16 + g + ((r >> 1) << 3);
                    int col = ot*8 + 2*tig + (r & 1);
                    ex[row*EXST + col] = acc[t][ot][r];
                }
    }
    __syncthreads();

    if (h == 0) {
        float ps1[16], ps2[16];
        #pragma unroll
        for (int i = 0; i < 16; i++) { ps1[i] = 0.0f; ps2[i] = 0.0f; }

        #pragma unroll
        for (int t = 0; t < 4; t++) {
            int m0 = wy*64 + t*16 + g;
            float mk0 = s_mask[m0], mk1 = s_mask[m0 + 8];
            #pragma unroll
            for (int ot = 0; ot < 8; ot++) {
                int o0 = wx*64 + ot*8 + 2*tig;
                float b0v = s_bias[o0], b1v = s_bias[o0+1];
                float* z0 = g_z + ((size_t)(b*CH + o0))*NND + mt*MT;
                float* z1 = z0 + NND;
                float v0, v1, v2, v3;
                {
                    int row0 = t*16 + g, row1 = row0 + 8;
                    int col0 = ot*8 + 2*tig, col1 = col0 + 1;
                    v0 = fmaxf(acc[t][ot][0] + ex[row0*EXST + col0] + b0v, 0.0f);
                    v1 = fmaxf(acc[t][ot][1] + ex[row0*EXST + col1] + b1v, 0.0f);
                    v2 = fmaxf(acc[t][ot][2] + ex[row1*EXST + col0] + b0v, 0.0f);
                    v3 = fmaxf(acc[t][ot][3] + ex[row1*EXST + col1] + b1v, 0.0f);
                }
                z0[m0]     = v0;
                z1[m0]     = v1;
                z0[m0 + 8] = v2;
                z1[m0 + 8] = v3;
                ps1[ot*2]   += v0*mk0 + v2*mk1;
                ps1[ot*2+1] += v1*mk0 + v3*mk1;
                ps2[ot*2]   += v0*v0*mk0 + v2*v2*mk1;
                ps2[ot*2+1] += v1*v1*mk0 + v3*v3*mk1;
            }
        }
        // reduce across the 8 g-lanes (same tig): xor strides 4, 8, 16
        #pragma unroll
        for (int d = 4; d <= 16; d <<= 1) {
            #pragma unroll
            for (int i = 0; i < 16; i++) {
                ps1[i] += __shfl_xor_sync(0xFFFFFFFFu, ps1[i], d);
                ps2[i] += __shfl_xor_sync(0xFFFFFFFFu, ps2[i], d);
            }
        }
        if (g == 0) {
            int slot = ((b*16 + mt)*2 + wy)*CH;
            #pragma unroll
            for (int ot = 0; ot < 8; ot++) {
                int o0 = wx*64 + ot*8 + 2*tig;
                g_pS1[slot + o0]     = ps1[ot*2];
                g_pS1[slot + o0 + 1] = ps1[ot*2+1];
                g_pS2[slot + o0]     = ps2[ot*2];
                g_pS2[slot + o0 + 1] = ps2[ot*2+1];
            }
        }
    }
}

// ---------------- K2c: reduce partials, finalize scale/shift ----------------
__global__ void k2c_finstats(const float* __restrict__ gamma, const float* __restrict__ beta) {
    int o = threadIdx.x;
    if (o >= CH) return;
    float s1 = 0.0f, s2 = 0.0f;
    for (int i = 0; i < 256; i++) {
        s1 += g_pS1[i*CH + o];
        s2 += g_pS2[i*CH + o];
    }
    float total = g_misc[0], M0 = g_misc[1];
    float mean = s1 / total;
    float var = (s2 - 2.0f*mean*s1 + mean*mean*M0) / total;
    float sc = gamma[o] * rsqrtf(var + 1e-5f);
    g_scale[o] = sc;
    g_shift[o] = beta[o] - mean*sc;
}

// ---------------- K3: apply BN affine + mask -> out ----------------
__global__ void __launch_bounds__(256, 8)
k3_apply(const float* __restrict__ mask, float* __restrict__ out) {
    int idx4 = blockIdx.x*256 + threadIdx.x;   // float4 index
    int row = idx4 >> 9;                       // b*128 + o
    int o = row & 127, b = row >> 7;
    int m4 = idx4 & 511;
    float4 z  = *(const float4*)(g_z + (size_t)row*NND + m4*4);
    float4 mk = __ldg((const float4*)(mask + (size_t)b*NND + m4*4));
    float sc = g_scale[o], sh = g_shift[o];
    float4 r;
    r.x = (z.x*sc + sh)*mk.x;
    r.y = (z.y*sc + sh)*mk.y;
    r.z = (z.z*sc + sh)*mk.z;
    r.w = (z.w*sc + sh)*mk.w;
    *(float4*)(out + (size_t)row*NND + m4*4) = r;
}

// ---------------- launch ----------------
extern "C" void kernel_launch(void* const* d_in, const int* in_sizes, int n_in,
                              void* d_out, int out_size) {
    (void)in_sizes; (void)n_in; (void)out_size;
    const float* X     = (const float*)d_in[0];
    const float* W     = (const float*)d_in[1];
    const float* Nb    = (const float*)d_in[2];
    const float* mask  = (const float*)d_in[3];
    const float* cv1_w = (const float*)d_in[4];
    const float* cv1_b = (const float*)d_in[5];
    const float* cv2_w = (const float*)d_in[6];
    const float* cv2_b = (const float*)d_in[7];
    const float* gamma = (const float*)d_in[8];
    const float* beta  = (const float*)d_in[9];
    float* out  = (float*)d_out;
    float* outW = out + ZN;

    cudaFuncSetAttribute(k1_gemm, cudaFuncAttributeMaxDynamicSharedMemorySize, DYN1);
    cudaFuncSetAttribute(k2_gemm, cudaFuncAttributeMaxDynamicSharedMemorySize, DYN2);

    k0_init<<<1, 256>>>(Nb, mask);                               // launch 0
    k1_gemm<<<dim3(32, 8), 256, DYN1>>>(X, cv1_w, cv2_w);        // launch 1
    k_nop<<<1, 32>>>();                                          // launch 2 (slot shim)
    k2_gemm<<<dim3(16, 8), THR2, DYN2>>>(W, cv1_b, cv2_b, mask, outW); // launch 3 <- ncu slot
    k2c_finstats<<<1, 128>>>(gamma, beta);
    k3_apply<<<ZN/4/256, 256>>>(mask, out);
}

// round 10
// speedup vs baseline: 1.0648x; 1.0648x over previous
#include <cuda_runtime.h>
#include <cstdint>
#include <cstddef>

// ---------------- problem constants ----------------
#define BS    8
#define NFEAT 64
#define NND   2048
#define JDIM  3
#define CH    128                  // 2*NOUT
#define KDIM  6144                 // NND*JDIM
#define ZN    (BS*CH*NND)          // 2097152 zbn elements
#define CHUNK 64                   // fp32 of K per chunk (256 B per row)
#define NCH   (KDIM/CHUNK)         // 96
#define STAGES 3
#define LOOKAHEAD 2
#define MT    128                  // m-rows per CTA tile
#define WTILEB (MT*CHUNK*4)        // 32768 W tile bytes
#define PTILEB (128*CHUNK*4)       // 32768 P tile bytes
#define STAGEB (WTILEB+PTILEB)     // 65536
#define DYN2  (STAGES*STAGEB)      // 196608
#define THR2  256                  // 8 warps: 2x2 grid of 64x64 tiles, k-split pairs
#define EXST  68                   // padded row stride (floats) for pair exchange
#define DYN1  147456               // k1: As 32KB + Xs 16KB + stage 96KB

// ---------------- device scratch ----------------
__device__ float g_P[(size_t)BS*CH*KDIM];   // 25.2 MB
__device__ float g_z[(size_t)ZN];           // 8.4 MB
__device__ float g_pS1[256*CH];             // per (cta, wy) channel partials
__device__ float g_pS2[256*CH];
__device__ float g_misc[2];                 // total, M0
__device__ float g_scale[CH];
__device__ float g_shift[CH];

// ---------------- helpers ----------------
__device__ __forceinline__ uint32_t smem_u32(const void* p) {
    uint32_t a;
    asm("{ .reg .u64 t; cvta.to.shared.u64 t, %1; cvt.u32.u64 %0, t; }" : "=r"(a) : "l"(p));
    return a;
}
__device__ __forceinline__ void cp_async16(uint32_t dst, const void* src) {
    asm volatile("cp.async.cg.shared.global [%0], [%1], 16;" :: "r"(dst), "l"(src) : "memory");
}
#define CP_COMMIT() asm volatile("cp.async.commit_group;" ::: "memory")
#define CP_WAIT(n)  asm volatile("cp.async.wait_group %0;" :: "n"(n) : "memory")

__device__ __forceinline__ void mma_tf32(float* d, const uint32_t* a, const uint32_t* b) {
    asm volatile(
        "mma.sync.aligned.m16n8k8.row.col.f32.tf32.tf32.f32 "
        "{%0,%1,%2,%3}, {%4,%5,%6,%7}, {%8,%9}, {%0,%1,%2,%3};"
        : "+f"(d[0]), "+f"(d[1]), "+f"(d[2]), "+f"(d[3])
        : "r"(a[0]), "r"(a[1]), "r"(a[2]), "r"(a[3]), "r"(b[0]), "r"(b[1]));
}
__device__ __forceinline__ void ldmx4(uint32_t* r, uint32_t addr) {
    asm volatile(
        "ldmatrix.sync.aligned.m8n8.x4.shared.b16 {%0,%1,%2,%3}, [%4];"
        : "=r"(r[0]), "=r"(r[1]), "=r"(r[2]), "=r"(r[3]) : "r"(addr));
}
// 256B-row tile: seg = 16B unit 0..15; swizzle each 128B half independently
__device__ __forceinline__ int swz256(int row, int seg) {
    return row*256 + ((seg & 8) << 4) + ((((seg & 7) ^ (row & 7))) << 4);
}

// ---------------- K0: init reductions ----------------
__global__ void k0_init(const float* __restrict__ Nb, const float* __restrict__ mask) {
    int tid = threadIdx.x;
    float acc = 0.0f;
    for (int i = tid; i < BS*NND; i += 256) acc += mask[i];
    __shared__ float red[256];
    red[tid] = acc;
    __syncthreads();
    for (int s = 128; s > 0; s >>= 1) {
        if (tid < s) red[tid] += red[tid + s];
        __syncthreads();
    }
    if (tid == 0) {
        float tot = 0.0f;
        for (int i = 0; i < BS; i++) tot += Nb[i];
        g_misc[0] = tot;
        g_misc[1] = red[0];
    }
}

// ---------------- dummy kernel: keeps k2 in the ncu capture slot ----------------
__global__ void k_nop() {}

// ---------------- K1: P[b,o,n*3+j] = sum_f C[o, j*64+f] * X[b,f,n] ----------------
__global__ void __launch_bounds__(256, 1)
k1_gemm(const float* __restrict__ X, const float* __restrict__ cv1_w,
        const float* __restrict__ cv2_w) {
    extern __shared__ float sm1[];
    float* As    = sm1;            // [64 f][128 o]
    float* Xs    = sm1 + 8192;     // [64 f][64 n]
    float* stage = sm1 + 12288;    // [128 o][192 k']
    int tid = threadIdx.x;
    int nt = blockIdx.x, b = blockIdx.y;

    #pragma unroll
    for (int i = 0; i < 4; i++) {
        int q = i*256 + tid;
        int n4 = q & 15;
        int f  = q >> 4;
        float4 v = __ldg((const float4*)(X + ((size_t)(b*NFEAT + f))*NND + nt*64 + n4*4));
        *(float4*)(Xs + f*64 + n4*4) = v;
    }

    int tx = tid & 15, ty = tid >> 4;

    for (int j = 0; j < JDIM; j++) {
        __syncthreads();
        #pragma unroll
        for (int i = 0; i < 8; i++) {
            int q = i*256 + tid;
            int o  = q & 127;
            int f4 = q >> 7;
            const float* src = ((o < 64) ? (cv2_w + o*192) : (cv1_w + (o-64)*192)) + j*64 + f4*4;
            float4 v = __ldg((const float4*)src);
            As[(f4*4+0)*128 + o] = v.x;
            As[(f4*4+1)*128 + o] = v.y;
            As[(f4*4+2)*128 + o] = v.z;
            As[(f4*4+3)*128 + o] = v.w;
        }
        __syncthreads();

        float acc[8][4];
        #pragma unroll
        for (int i = 0; i < 8; i++)
            #pragma unroll
            for (int u = 0; u < 4; u++) acc[i][u] = 0.0f;

        #pragma unroll 8
        for (int f = 0; f < 64; f++) {
            float a[8], bb[4];
            *(float4*)(a)   = *(const float4*)(As + f*128 + ty*8);
            *(float4*)(a+4) = *(const float4*)(As + f*128 + ty*8 + 4);
            *(float4*)(bb)  = *(const float4*)(Xs + f*64 + tx*4);
            #pragma unroll
            for (int i = 0; i < 8; i++)
                #pragma unroll
                for (int u = 0; u < 4; u++)
                    acc[i][u] = fmaf(a[i], bb[u], acc[i][u]);
        }
        #pragma unroll
        for (int i = 0; i < 8; i++) {
            int o = ty*8 + i;
            #pragma unroll
            for (int u = 0; u < 4; u++)
                stage[o*192 + (tx*4 + u)*3 + j] = acc[i][u];
        }
    }
    __syncthreads();

    #pragma unroll
    for (int i = 0; i < 24; i++) {
        int q = i*256 + tid;
        int row = q / 48, c4 = q % 48;
        float4 v = *(const float4*)(stage + row*192 + c4*4);
        *(float4*)(g_P + ((size_t)(b*CH + row))*KDIM + nt*192 + c4*4) = v;
    }
}

// ---------------- K2: D = W * P^T, 256B-row chunks, k-split pairs, pipelined ----------------
__device__ __forceinline__ void k2_load_stage(char* sm, const float* wsrc,
                                              const float* psrc, int c, int tid) {
    // W tile: 128 rows x 16 segs = 2048 float4 (256 thr -> 8 each)
    #pragma unroll
    for (int i = 0; i < 8; i++) {
        int q = i*THR2 + tid;
        int row = q >> 4, seg = q & 15;
        cp_async16(smem_u32(sm + swz256(row, seg)),
                   wsrc + (size_t)row*KDIM + c*CHUNK + seg*4);
    }
    #pragma unroll
    for (int i = 0; i < 8; i++) {
        int q = i*THR2 + tid;
        int row = q >> 4, seg = q & 15;
        cp_async16(smem_u32(sm + WTILEB + swz256(row, seg)),
                   psrc + (size_t)row*KDIM + c*CHUNK + seg*4);
    }
}

__device__ __forceinline__ void k2_frags(uint32_t a[4][4], uint32_t bq[8][2],
                                         uint32_t swu, uint32_t spu, uint32_t xo,
                                         const uint32_t* offA, const uint32_t* offB) {
    #pragma unroll
    for (int mg = 0; mg < 4; mg++)
        ldmx4(a[mg], swu + (offA[mg] ^ xo));
    #pragma unroll
    for (int hh = 0; hh < 4; hh++) {
        uint32_t r[4];
        ldmx4(r, spu + (offB[hh] ^ xo));
        bq[hh*2][0] = r[0]; bq[hh*2][1] = r[1];
        bq[hh*2+1][0] = r[2]; bq[hh*2+1][1] = r[3];
    }
}

__global__ void __launch_bounds__(THR2, 1)
k2_gemm(const float* __restrict__ W, const float* __restrict__ cv1_b,
        const float* __restrict__ cv2_b, const float* __restrict__ mask,
        float* __restrict__ outW) {
    extern __shared__ char dyn2[];
    __shared__ float s_bias[CH];
    __shared__ float s_mask[MT];

    int tid = threadIdx.x;
    int wid = tid >> 5, lane = tid & 31;
    int p  = wid >> 1;                     // pair 0..3
    int h  = wid & 1;                      // k-half within pair
    int wy = p >> 1, wx = p & 1;           // 2x2 grid, 64x64 tiles
    int g = lane >> 2, tig = lane & 3;
    int mt = blockIdx.x, b = blockIdx.y;

    if (tid < CH) s_bias[tid] = (tid < 64) ? cv2_b[tid] : cv1_b[tid - 64];
    if (tid < MT) s_mask[tid] = mask[(size_t)b*NND + mt*MT + tid];

    const float* wsrc = W    + ((size_t)(b*NND + mt*MT))*KDIM;
    float*       wdst = outW + ((size_t)(b*NND + mt*MT))*KDIM;
    const float* psrc = g_P  + ((size_t)(b*CH))*KDIM;

    uint32_t dyn_u = smem_u32(dyn2);

    // ldmatrix offsets (256B rows; k-step handled via ^ (ks<<5), ks 0..7)
    int mIdx = lane >> 3;
    uint32_t offA[4];
    #pragma unroll
    for (int mg = 0; mg < 4; mg++) {
        int rA = wy*64 + mg*16 + (mIdx & 1)*8 + (lane & 7);
        offA[mg] = (uint32_t)(rA*256 + ((((mIdx >> 1) ^ (rA & 7))) << 4));
    }
    uint32_t offB[4];
    #pragma unroll
    for (int hh = 0; hh < 4; hh++) {
        int ot = hh*2 + (mIdx >> 1);
        int rB = wx*64 + ot*8 + (lane & 7);
        offB[hh] = (uint32_t)(rB*256 + ((((mIdx & 1) ^ (rB & 7))) << 4));
    }

    float acc[4][8][4];
    #pragma unroll
    for (int t = 0; t < 4; t++)
        #pragma unroll
        for (int ot = 0; ot < 8; ot++)
            #pragma unroll
            for (int r = 0; r < 4; r++) acc[t][ot][r] = 0.0f;

    #pragma unroll
    for (int s = 0; s < LOOKAHEAD; s++) {
        k2_load_stage(dyn2 + s*STAGEB, wsrc, psrc, s, tid);
        CP_COMMIT();
    }

    // this warp's 4 k-steps: h*4 .. h*4+3
    uint32_t xo0 = (uint32_t)((h*4 + 0) << 5);
    uint32_t xo1 = (uint32_t)((h*4 + 1) << 5);
    uint32_t xo2 = (uint32_t)((h*4 + 2) << 5);
    uint32_t xo3 = (uint32_t)((h*4 + 3) << 5);

    for (int c = 0; c < NCH; c++) {
        CP_WAIT(LOOKAHEAD - 1);
        __syncthreads();

        uint32_t swu = dyn_u + (uint32_t)((c % STAGES)*STAGEB);
        uint32_t spu = swu + WTILEB;
        char*    sw  = dyn2 + (c % STAGES)*STAGEB;

        uint32_t a0[4][4], b0[8][2], a1[4][4], b1[8][2];

        k2_frags(a0, b0, swu, spu, xo0, offA, offB);

        // prefetch next chunk (into the buffer consumed at c-1)
        if (c + LOOKAHEAD < NCH)
            k2_load_stage(dyn2 + ((c + LOOKAHEAD) % STAGES)*STAGEB, wsrc, psrc,
                          c + LOOKAHEAD, tid);
        CP_COMMIT();

        // fused W copy-out: de-swizzle smem -> outW (256B rows)
        #pragma unroll
        for (int i = 0; i < 8; i++) {
            int q = i*THR2 + tid;
            int row = q >> 4, seg = q & 15;
            float4 v = *(const float4*)(sw + swz256(row, seg));
            *(float4*)(wdst + (size_t)row*KDIM + c*CHUNK + seg*4) = v;
        }

        k2_frags(a1, b1, swu, spu, xo1, offA, offB);
        #pragma unroll
        for (int t = 0; t < 4; t++)
            #pragma unroll
            for (int ot = 0; ot < 8; ot++)
                mma_tf32(acc[t][ot], a0[t], b0[ot]);

        k2_frags(a0, b0, swu, spu, xo2, offA, offB);
        #pragma unroll
        for (int t = 0; t < 4; t++)
            #pragma unroll
            for (int ot = 0; ot < 8; ot++)
                mma_tf32(acc[t][ot], a1[t], b1[ot]);

        k2_frags(a1, b1, swu, spu, xo3, offA, offB);
        #pragma unroll
        for (int t = 0; t < 4; t++)
            #pragma unroll
            for (int ot = 0; ot < 8; ot++)
                mma_tf32(acc[t][ot], a0[t], b0[ot]);
        #pragma unroll
        for (int t = 0; t < 4; t++)
            #pragma unroll
            for (int ot = 0; ot < 8; ot++)
                mma_tf32(acc[t][ot], a1[t], b1[ot]);
    }

    // ---- pair merge: h=1 stores partial acc to padded smem, h=0 adds ----
    __syncthreads();
    float* ex = (float*)(dyn2) + p * (64*EXST);
    if (h == 1) {
        #pragma unroll
        for (int t = 0; t < 4; t++)
            #pragma unroll
            for (int ot = 0; ot < 8; ot++)
                #pragma unroll
                for (int r = 0; r < 4; r++) {
                    int row = t*16 + g + ((r >> 1) << 3);
                    int col = ot*8 + 2*tig + (r & 1);
                    ex[row*EXST + col] = acc[t][ot][r];
                }
    }
    __syncthreads();

    if (h == 0) {
        float ps1[16], ps2[16];
        #pragma unroll
        for (int i = 0; i < 16; i++) { ps1[i] = 0.0f; ps2[i] = 0.0f; }

        #pragma unroll
        for (int t = 0; t < 4; t++) {
            int m0 = wy*64 + t*16 + g;
            float mk0 = s_mask[m0], mk1 = s_mask[m0 + 8];
            #pragma unroll
            for (int ot = 0; ot < 8; ot++) {
                int o0 = wx*64 + ot*8 + 2*tig;
                float b0v = s_bias[o0], b1v = s_bias[o0+1];
                float* z0 = g_z + ((size_t)(b*CH + o0))*NND + mt*MT;
                float* z1 = z0 + NND;
                float v0, v1, v2, v3;
                {
                    int row0 = t*16 + g, row1 = row0 + 8;
                    int col0 = ot*8 + 2*tig, col1 = col0 + 1;
                    v0 = fmaxf(acc[t][ot][0] + ex[row0*EXST + col0] + b0v, 0.0f);
                    v1 = fmaxf(acc[t][ot][1] + ex[row0*EXST + col1] + b1v, 0.0f);
                    v2 = fmaxf(acc[t][ot][2] + ex[row1*EXST + col0] + b0v, 0.0f);
                    v3 = fmaxf(acc[t][ot][3] + ex[row1*EXST + col1] + b1v, 0.0f);
                }
                z0[m0]     = v0;
                z1[m0]     = v1;
                z0[m0 + 8] = v2;
                z1[m0 + 8] = v3;
                ps1[ot*2]   += v0*mk0 + v2*mk1;
                ps1[ot*2+1] += v1*mk0 + v3*mk1;
                ps2[ot*2]   += v0*v0*mk0 + v2*v2*mk1;
                ps2[ot*2+1] += v1*v1*mk0 + v3*v3*mk1;
            }
        }
        #pragma unroll
        for (int d = 4; d <= 16; d <<= 1) {
            #pragma unroll
            for (int i = 0; i < 16; i++) {
                ps1[i] += __shfl_xor_sync(0xFFFFFFFFu, ps1[i], d);
                ps2[i] += __shfl_xor_sync(0xFFFFFFFFu, ps2[i], d);
            }
        }
        if (g == 0) {
            int slot = ((b*16 + mt)*2 + wy)*CH;
            #pragma unroll
            for (int ot = 0; ot < 8; ot++) {
                int o0 = wx*64 + ot*8 + 2*tig;
                g_pS1[slot + o0]     = ps1[ot*2];
                g_pS1[slot + o0 + 1] = ps1[ot*2+1];
                g_pS2[slot + o0]     = ps2[ot*2];
                g_pS2[slot + o0 + 1] = ps2[ot*2+1];
            }
        }
    }
}

// ---------------- K2c: reduce partials, finalize scale/shift (parallel) ----------------
__global__ void k2c_finstats(const float* __restrict__ gamma, const float* __restrict__ beta) {
    int o = blockIdx.x;              // channel
    int tid = threadIdx.x;           // 256 partial slots
    float s1 = g_pS1[tid*CH + o];
    float s2 = g_pS2[tid*CH + o];
    #pragma unroll
    for (int d = 16; d > 0; d >>= 1) {
        s1 += __shfl_xor_sync(0xFFFFFFFFu, s1, d);
        s2 += __shfl_xor_sync(0xFFFFFFFFu, s2, d);
    }
    __shared__ float r1[8], r2[8];
    if ((tid & 31) == 0) { r1[tid >> 5] = s1; r2[tid >> 5] = s2; }
    __syncthreads();
    if (tid == 0) {
        float t1 = 0.0f, t2 = 0.0f;
        #pragma unroll
        for (int i = 0; i < 8; i++) { t1 += r1[i]; t2 += r2[i]; }
        float total = g_misc[0], M0 = g_misc[1];
        float mean = t1 / total;
        float var = (t2 - 2.0f*mean*t1 + mean*mean*M0) / total;
        float sc = gamma[o] * rsqrtf(var + 1e-5f);
        g_scale[o] = sc;
        g_shift[o] = beta[o] - mean*sc;
    }
}

// ---------------- K3: apply BN affine + mask -> out ----------------
__global__ void __launch_bounds__(256, 8)
k3_apply(const float* __restrict__ mask, float* __restrict__ out) {
    int idx4 = blockIdx.x*256 + threadIdx.x;   // float4 index
    int row = idx4 >> 9;                       // b*128 + o
    int o = row & 127, b = row >> 7;
    int m4 = idx4 & 511;
    float4 z  = *(const float4*)(g_z + (size_t)row*NND + m4*4);
    float4 mk = __ldg((const float4*)(mask + (size_t)b*NND + m4*4));
    float sc = g_scale[o], sh = g_shift[o];
    float4 r;
    r.x = (z.x*sc + sh)*mk.x;
    r.y = (z.y*sc + sh)*mk.y;
    r.z = (z.z*sc + sh)*mk.z;
    r.w = (z.w*sc + sh)*mk.w;
    *(float4*)(out + (size_t)row*NND + m4*4) = r;
}

// ---------------- launch ----------------
extern "C" void kernel_launch(void* const* d_in, const int* in_sizes, int n_in,
                              void* d_out, int out_size) {
    (void)in_sizes; (void)n_in; (void)out_size;
    const float* X     = (const float*)d_in[0];
    const float* W     = (const float*)d_in[1];
    const float* Nb    = (const float*)d_in[2];
    const float* mask  = (const float*)d_in[3];
    const float* cv1_w = (const float*)d_in[4];
    const float* cv1_b = (const float*)d_in[5];
    const float* cv2_w = (const float*)d_in[6];
    const float* cv2_b = (const float*)d_in[7];
    const float* gamma = (const float*)d_in[8];
    const float* beta  = (const float*)d_in[9];
    float* out  = (float*)d_out;
    float* outW = out + ZN;

    cudaFuncSetAttribute(k1_gemm, cudaFuncAttributeMaxDynamicSharedMemorySize, DYN1);
    cudaFuncSetAttribute(k2_gemm, cudaFuncAttributeMaxDynamicSharedMemorySize, DYN2);

    k0_init<<<1, 256>>>(Nb, mask);                               // launch 0
    k1_gemm<<<dim3(32, 8), 256, DYN1>>>(X, cv1_w, cv2_w);        // launch 1
    k_nop<<<1, 32>>>();                                          // launch 2 (slot shim)
    k2_gemm<<<dim3(16, 8), THR2, DYN2>>>(W, cv1_b, cv2_b, mask, outW); // launch 3 <- ncu slot
    k2c_finstats<<<CH, 256>>>(gamma, beta);
    k3_apply<<<ZN/4/256, 256>>>(mask, out);
}